// round 9
// baseline (speedup 1.0000x reference)
#include <cuda_runtime.h>
#include <cuda_fp16.h>
#include <stdint.h>
#include <math.h>
#include <float.h>
#include <limits.h>

#define BATCH 2
#define SEQ   8192
#define DIM   1024
#define HEADS 8
#define DH    64
#define HDH   512
#define WIN   64
#define NWIN  128
#define NQ    1024
#define NKV   2048
#define NITER 50
#define NTOK  (BATCH*SEQ)
#define NKEY  (NKV+1)
#define NKEYP 2112          // padded to 64-key chunks

// GEMM tiling
#define GBM 128
#define GBN 128
#define GBK 64
#define AS_STRIDE 72        // halfs per A row (64 + 8 pad)
#define BS_STRIDE 136       // halfs per B row (128 + 8 pad)
#define STAGE_HALFS (GBM*AS_STRIDE + GBK*BS_STRIDE)   // 9216 + 8704 = 17920
#define SMEM_GEMM (3 * STAGE_HALFS * 2)               // 107520 bytes

// ---------------- scratch ----------------
__device__ __half g_xnh[(size_t)NTOK*DIM];
__device__ float g_rms[NTOK];
__device__ float g_s[2][NTOK];
__device__ __half g_qkvh[(size_t)NTOK*(3*HDH)];
__device__ __half g_loh[(size_t)NTOK*HDH];
__device__ int   g_iq[BATCH][NQ];
__device__ float g_sq[BATCH][NQ];
__device__ int   g_ikv[BATCH][NKV];
__device__ float g_skv[BATCH][NKV];
__device__ int   g_qpos[NTOK];
__device__ __half g_xqnh[(size_t)BATCH*NQ*DIM];
__device__ __half g_xkvnh[(size_t)BATCH*NKV*DIM];
__device__ __half g_qhh[(size_t)BATCH*NQ*HDH];
__device__ float g_kvh[(size_t)BATCH*NKV*DIM];
__device__ __half g_khh[(size_t)BATCH*HEADS*NKEYP*DH];
__device__ __half g_vhh[(size_t)BATCH*HEADS*NKEYP*DH];
__device__ __half g_hoh[(size_t)BATCH*NQ*HDH];
__device__ float g_routed[(size_t)BATCH*NQ*DIM];
// fp16 weights
__device__ __half g_wqkvh[(size_t)DIM*3*HDH];
__device__ __half g_wolh[(size_t)HDH*DIM];
__device__ __half g_wqh[(size_t)DIM*HDH];
__device__ __half g_wkvh[(size_t)DIM*DIM];
__device__ __half g_wohh[(size_t)HDH*DIM];

// ---------------- asm helpers ----------------
__device__ __forceinline__ unsigned saddr(const void* p) {
    return (unsigned)__cvta_generic_to_shared(p);
}
__device__ __forceinline__ void cp16(unsigned dst, const void* src) {
    asm volatile("cp.async.cg.shared.global [%0], [%1], 16;" :: "r"(dst), "l"(src));
}
__device__ __forceinline__ void ldsm_x4(unsigned* r, unsigned a) {
    asm volatile("ldmatrix.sync.aligned.m8n8.x4.shared.b16 {%0,%1,%2,%3}, [%4];"
        : "=r"(r[0]), "=r"(r[1]), "=r"(r[2]), "=r"(r[3]) : "r"(a));
}
__device__ __forceinline__ void ldsm_x2(unsigned* r, unsigned a) {
    asm volatile("ldmatrix.sync.aligned.m8n8.x2.shared.b16 {%0,%1}, [%2];"
        : "=r"(r[0]), "=r"(r[1]) : "r"(a));
}
__device__ __forceinline__ void ldsm_x2t(unsigned* r, unsigned a) {
    asm volatile("ldmatrix.sync.aligned.m8n8.x2.trans.shared.b16 {%0,%1}, [%2];"
        : "=r"(r[0]), "=r"(r[1]) : "r"(a));
}
__device__ __forceinline__ void mma16816(float* d, const unsigned* a, const unsigned* b) {
    asm volatile("mma.sync.aligned.m16n8k16.row.col.f32.f16.f16.f32 "
        "{%0,%1,%2,%3}, {%4,%5,%6,%7}, {%8,%9}, {%0,%1,%2,%3};"
        : "+f"(d[0]), "+f"(d[1]), "+f"(d[2]), "+f"(d[3])
        : "r"(a[0]), "r"(a[1]), "r"(a[2]), "r"(a[3]), "r"(b[0]), "r"(b[1]));
}
__device__ __forceinline__ unsigned h2pack(float x, float y) {
    __half2 t = __floats2half2_rn(x, y);
    return *(unsigned*)&t;
}

// ---------------- reductions ----------------
__device__ __forceinline__ float bsum256(float v, float* sh) {
    int lane = threadIdx.x & 31, w = threadIdx.x >> 5;
    #pragma unroll
    for (int o = 16; o; o >>= 1) v += __shfl_xor_sync(0xffffffffu, v, o);
    __syncthreads();
    if (lane == 0) sh[w] = v;
    __syncthreads();
    float r = sh[0];
    #pragma unroll
    for (int i = 1; i < 8; i++) r += sh[i];
    return r;
}
__device__ __forceinline__ float bsum1024(float v, float* sh) {
    int lane = threadIdx.x & 31, w = threadIdx.x >> 5;
    #pragma unroll
    for (int o = 16; o; o >>= 1) v += __shfl_xor_sync(0xffffffffu, v, o);
    __syncthreads();
    if (lane == 0) sh[w] = v;
    __syncthreads();
    float r = sh[0];
    #pragma unroll
    for (int i = 1; i < 32; i++) r += sh[i];
    return r;
}
__device__ __forceinline__ float bmax1024(float v, float* sh) {
    int lane = threadIdx.x & 31, w = threadIdx.x >> 5;
    #pragma unroll
    for (int o = 16; o; o >>= 1) v = fmaxf(v, __shfl_xor_sync(0xffffffffu, v, o));
    __syncthreads();
    if (lane == 0) sh[w] = v;
    __syncthreads();
    float r = sh[0];
    #pragma unroll
    for (int i = 1; i < 32; i++) r = fmaxf(r, sh[i]);
    return r;
}

// ---------------- 1. layernorm + routing dots + qpos init ----------------
__global__ __launch_bounds__(256) void k_ln(const float* __restrict__ x,
        const float* __restrict__ ln_g, const float* __restrict__ ln_b,
        const float* __restrict__ rt_q, const float* __restrict__ rt_kv) {
    __shared__ float sh[32];
    __shared__ float s_mean, s_inv;
    int row = blockIdx.x;
    const float* xr = x + (size_t)row * DIM;
    int tid = threadIdx.x;
    float v[4], s = 0.f, ss = 0.f, dq = 0.f, dk = 0.f;
    #pragma unroll
    for (int u = 0; u < 4; u++) {
        int i = tid + 256 * u;
        float t = xr[i];
        v[u] = t; s += t; ss += t * t; dq += t * rt_q[i]; dk += t * rt_kv[i];
    }
    s  = bsum256(s, sh);
    ss = bsum256(ss, sh);
    dq = bsum256(dq, sh);
    dk = bsum256(dk, sh);
    if (tid == 0) {
        float mean = s * (1.0f / DIM);
        float var  = ss * (1.0f / DIM) - mean * mean;
        s_mean = mean;
        s_inv  = 1.0f / sqrtf(var + 1e-5f);
        g_rms[row] = 32.0f / fmaxf(sqrtf(ss), 1e-12f);
        g_s[0][row] = dq;
        g_s[1][row] = dk;
        g_qpos[row] = -1;
    }
    __syncthreads();
    float mean = s_mean, inv = s_inv;
    #pragma unroll
    for (int u = 0; u < 4; u++) {
        int i = tid + 256 * u;
        g_xnh[(size_t)row * DIM + i] = __float2half((v[u] - mean) * inv * ln_g[i] + ln_b[i]);
    }
}

// ---------------- 2. all weight converts in one kernel ----------------
#define NW1 (DIM*3*HDH)
#define NW2 (HDH*DIM)
#define NW3 (DIM*HDH)
#define NW4 (DIM*DIM)
#define NW5 (HDH*DIM)
__global__ void k_f2h_all(const float* w1, const float* w2, const float* w3,
                          const float* w4, const float* w5) {
    int total = NW1 + NW2 + NW3 + NW4 + NW5;
    for (int i = blockIdx.x * blockDim.x + threadIdx.x; i < total; i += gridDim.x * blockDim.x) {
        int j = i;
        if (j < NW1) { g_wqkvh[j] = __float2half(w1[j]); continue; } j -= NW1;
        if (j < NW2) { g_wolh[j]  = __float2half(w2[j]); continue; } j -= NW2;
        if (j < NW3) { g_wqh[j]   = __float2half(w3[j]); continue; } j -= NW3;
        if (j < NW4) { g_wkvh[j]  = __float2half(w4[j]); continue; } j -= NW4;
        g_wohh[j] = __float2half(w5[j]);
    }
}

// ---------------- 3. coor_descent + exact-tie-break top-k (bitonic) ----------------
__global__ __launch_bounds__(1024) void k_route() {
    extern __shared__ unsigned long long keys[];
    __shared__ float sh[32];
    int tid = threadIdx.x;
    int b = blockIdx.x >> 1, route = blockIdx.x & 1;
    const float* sp = g_s[route] + b * SEQ;
    float s[8], bb[8];
    #pragma unroll
    for (int u = 0; u < 8; u++) { s[u] = sp[tid + 1024 * u]; bb[u] = -s[u]; }
    float logk = logf(route ? 2304.0f : 1152.0f);
    float a = 0.0f;
    for (int it = 0; it < NITER; it++) {
        float lm = -FLT_MAX;
        #pragma unroll
        for (int u = 0; u < 8; u++) lm = fmaxf(lm, s[u] + bb[u]);
        float m = bmax1024(lm, sh);
        float ls = 0.0f;
        #pragma unroll
        for (int u = 0; u < 8; u++) ls += expf(s[u] + bb[u] - m);
        float sum = bsum1024(ls, sh);
        a = logk - (logf(sum) + m);
        #pragma unroll
        for (int u = 0; u < 8; u++) bb[u] = -fmaxf(s[u] + a, 0.0f);
    }
    #pragma unroll
    for (int u = 0; u < 8; u++) {
        int idx = tid + 1024 * u;
        float sc = expf(s[u] + a + bb[u]);
        keys[idx] = ((unsigned long long)__float_as_uint(sc) << 32)
                  | (unsigned)(SEQ - 1 - idx);
    }
    __syncthreads();
    for (int k2 = 2; k2 <= SEQ; k2 <<= 1) {
        for (int j = k2 >> 1; j > 0; j >>= 1) {
            #pragma unroll
            for (int w = 0; w < 8; w++) {
                int i = tid + 1024 * w;
                int ixj = i ^ j;
                if (ixj > i) {
                    unsigned long long A = keys[i], B = keys[ixj];
                    bool sw = ((i & k2) == 0) ? (A < B) : (A > B);
                    if (sw) { keys[i] = B; keys[ixj] = A; }
                }
            }
            __syncthreads();
        }
    }
    int N = route ? NKV : NQ;
    for (int i = tid; i < N; i += 1024) {
        unsigned long long kk = keys[i];
        int idx = (SEQ - 1) - (int)(unsigned)(kk & 0xffffffffu);
        float sc = __uint_as_float((unsigned)(kk >> 32));
        float sel = sc + (1.0f - sc);
        if (route) { g_ikv[b][i] = idx; g_skv[b][i] = sel; }
        else       { g_iq[b][i] = idx;  g_sq[b][i] = sel; g_qpos[b * SEQ + idx] = i; }
    }
}

// ---------------- 4. gather + rmsnorm (fp16 out) ----------------
__global__ __launch_bounds__(256) void k_gather(const float* __restrict__ x,
                                                const float* __restrict__ rms_g) {
    int r = blockIdx.x, tid = threadIdx.x;
    int b, tok; __half* dst;
    if (r < BATCH * NQ) { b = r / NQ; tok = g_iq[b][r % NQ]; dst = g_xqnh + (size_t)r * DIM; }
    else { int r2 = r - BATCH * NQ; b = r2 / NKV; tok = g_ikv[b][r2 % NKV]; dst = g_xkvnh + (size_t)r2 * DIM; }
    const float* src = x + ((size_t)(b * SEQ) + tok) * DIM;
    float sc = g_rms[b * SEQ + tok];
    for (int i = tid; i < DIM; i += 256) dst[i] = __float2half(src[i] * sc * rms_g[i]);
}

// ---------------- 5. fp16 tensor-core GEMM: 128x128x64 tiles, 3-stage cp.async ----------------
template <typename OutT>
__global__ __launch_bounds__(256) void k_hgemm(const __half* __restrict__ A,
        const __half* __restrict__ B, OutT* __restrict__ C, int M, int N, int K) {
    extern __shared__ __half sm[];
    int tid = threadIdx.x, lane = tid & 31, wid = tid >> 5;
    int wm = (wid & 1) * 64, wn = (wid >> 1) * 32;
    // load mapping: 1024 cp.async of 16B per stage (4 per thread for A, 4 for B)
    int arow = tid >> 1, acol = (tid & 1) * 32;           // A: 2 threads/row, 4 cps each
    int brow = tid >> 2, bcol = (tid & 3) * 32;           // B: 4 threads/row, 4 cps each
    const __half* Ag = A + (size_t)(blockIdx.y * GBM) * K;
    const __half* Bg = B + blockIdx.x * GBN;
    float acc[4][4][4];
    #pragma unroll
    for (int mt = 0; mt < 4; mt++)
        #pragma unroll
        for (int nt = 0; nt < 4; nt++)
            #pragma unroll
            for (int i = 0; i < 4; i++) acc[mt][nt][i] = 0.0f;

    int nstage = K >> 6;
    // prologue: stages 0,1
    #pragma unroll
    for (int ps = 0; ps < 2; ps++) {
        __half* As = sm + ps * STAGE_HALFS;
        __half* Bs = As + GBM * AS_STRIDE;
        int k0 = ps << 6;
        const __half* a0 = Ag + (size_t)arow * K + k0 + acol;
        #pragma unroll
        for (int c = 0; c < 4; c++)
            cp16(saddr(&As[arow * AS_STRIDE + acol + c * 8]), a0 + c * 8);
        const __half* b0 = Bg + (size_t)(k0 + brow) * N + bcol;
        #pragma unroll
        for (int c = 0; c < 4; c++)
            cp16(saddr(&Bs[brow * BS_STRIDE + bcol + c * 8]), b0 + c * 8);
        asm volatile("cp.async.commit_group;");
    }
    for (int s = 0; s < nstage; s++) {
        if (s == nstage - 1) asm volatile("cp.async.wait_group 0;");
        else                 asm volatile("cp.async.wait_group 1;");
        __syncthreads();
        if (s + 2 < nstage) {
            int st = (s + 2) % 3;
            __half* As = sm + st * STAGE_HALFS;
            __half* Bs = As + GBM * AS_STRIDE;
            int k0 = (s + 2) << 6;
            const __half* a0 = Ag + (size_t)arow * K + k0 + acol;
            #pragma unroll
            for (int c = 0; c < 4; c++)
                cp16(saddr(&As[arow * AS_STRIDE + acol + c * 8]), a0 + c * 8);
            const __half* b0 = Bg + (size_t)(k0 + brow) * N + bcol;
            #pragma unroll
            for (int c = 0; c < 4; c++)
                cp16(saddr(&Bs[brow * BS_STRIDE + bcol + c * 8]), b0 + c * 8);
            asm volatile("cp.async.commit_group;");
        }
        int cur = s % 3;
        const __half* As = sm + cur * STAGE_HALFS;
        const __half* Bs = As + GBM * AS_STRIDE;
        #pragma unroll
        for (int kk = 0; kk < 64; kk += 16) {
            unsigned af[4][4], bf[4][2];
            #pragma unroll
            for (int mt = 0; mt < 4; mt++) {
                int row = wm + mt * 16 + (lane & 15);
                int col = kk + ((lane >> 4) & 1) * 8;
                ldsm_x4(af[mt], saddr(&As[row * AS_STRIDE + col]));
            }
            #pragma unroll
            for (int nt = 0; nt < 4; nt++) {
                int row = kk + (lane & 15);
                ldsm_x2t(bf[nt], saddr(&Bs[row * BS_STRIDE + wn + nt * 8]));
            }
            #pragma unroll
            for (int mt = 0; mt < 4; mt++)
                #pragma unroll
                for (int nt = 0; nt < 4; nt++)
                    mma16816(acc[mt][nt], af[mt], bf[nt]);
        }
        __syncthreads();
    }
    #pragma unroll
    for (int mt = 0; mt < 4; mt++) {
        int r = blockIdx.y * GBM + wm + mt * 16 + (lane >> 2);
        #pragma unroll
        for (int nt = 0; nt < 4; nt++) {
            int c = blockIdx.x * GBN + wn + nt * 8 + (lane & 3) * 2;
            if (sizeof(OutT) == 4) {
                *(float2*)((float*)C + (size_t)r * N + c)       = make_float2(acc[mt][nt][0], acc[mt][nt][1]);
                *(float2*)((float*)C + (size_t)(r + 8) * N + c) = make_float2(acc[mt][nt][2], acc[mt][nt][3]);
            } else {
                *(unsigned*)((__half*)C + (size_t)r * N + c)       = h2pack(acc[mt][nt][0], acc[mt][nt][1]);
                *(unsigned*)((__half*)C + (size_t)(r + 8) * N + c) = h2pack(acc[mt][nt][2], acc[mt][nt][3]);
            }
        }
    }
}

// ---------------- flash warp core: one 16-key block ----------------
__device__ __forceinline__ void flash_kb(const __half* sK, const __half* sV,
        int kb, int gkey, int firstInvalid,
        const unsigned (&af)[4][4], float (&o)[8][4], float (&m)[2], float (&l)[2], int lane) {
    float a0[4] = {0.f,0.f,0.f,0.f}, a1[4] = {0.f,0.f,0.f,0.f};
    #pragma unroll
    for (int kc = 0; kc < 4; kc++) {
        unsigned b0[2], b1[2];
        int r = lane & 7, cc = kc * 16 + ((lane >> 3) & 1) * 8;
        ldsm_x2(b0, saddr(&sK[(kb + r) * 72 + cc]));
        ldsm_x2(b1, saddr(&sK[(kb + 8 + r) * 72 + cc]));
        mma16816(a0, af[kc], b0);
        mma16816(a1, af[kc], b1);
    }
    #pragma unroll
    for (int i = 0; i < 4; i++) { a0[i] *= 0.125f; a1[i] *= 0.125f; }
    if (gkey + 16 > firstInvalid) {
        int c0 = gkey + ((lane & 3) << 1);
        if (c0     >= firstInvalid) { a0[0] = -1e30f; a0[2] = -1e30f; }
        if (c0 + 1 >= firstInvalid) { a0[1] = -1e30f; a0[3] = -1e30f; }
        if (c0 + 8 >= firstInvalid) { a1[0] = -1e30f; a1[2] = -1e30f; }
        if (c0 + 9 >= firstInvalid) { a1[1] = -1e30f; a1[3] = -1e30f; }
    }
    float mx0 = fmaxf(fmaxf(a0[0], a0[1]), fmaxf(a1[0], a1[1]));
    float mx1 = fmaxf(fmaxf(a0[2], a0[3]), fmaxf(a1[2], a1[3]));
    mx0 = fmaxf(mx0, __shfl_xor_sync(0xffffffffu, mx0, 1));
    mx0 = fmaxf(mx0, __shfl_xor_sync(0xffffffffu, mx0, 2));
    mx1 = fmaxf(mx1, __shfl_xor_sync(0xffffffffu, mx1, 1));
    mx1 = fmaxf(mx1, __shfl_xor_sync(0xffffffffu, mx1, 2));
    float nm0 = fmaxf(m[0], mx0), nm1 = fmaxf(m[1], mx1);
    float s0 = __expf(m[0] - nm0), s1 = __expf(m[1] - nm1);
    m[0] = nm0; m[1] = nm1;
    float p00 = __expf(a0[0] - nm0), p01 = __expf(a0[1] - nm0);
    float p02 = __expf(a1[0] - nm0), p03 = __expf(a1[1] - nm0);
    float p10 = __expf(a0[2] - nm1), p11 = __expf(a0[3] - nm1);
    float p12 = __expf(a1[2] - nm1), p13 = __expf(a1[3] - nm1);
    l[0] = l[0] * s0 + (p00 + p01 + p02 + p03);
    l[1] = l[1] * s1 + (p10 + p11 + p12 + p13);
    unsigned ap[4];
    ap[0] = h2pack(p00, p01);
    ap[1] = h2pack(p10, p11);
    ap[2] = h2pack(p02, p03);
    ap[3] = h2pack(p12, p13);
    #pragma unroll
    for (int nt = 0; nt < 8; nt++) {
        unsigned bv[2];
        ldsm_x2t(bv, saddr(&sV[(kb + (lane & 15)) * 72 + nt * 8]));
        o[nt][0] *= s0; o[nt][1] *= s0; o[nt][2] *= s1; o[nt][3] *= s1;
        mma16816(o[nt], ap, bv);
    }
}

// ---------------- 6. light windowed attention (tensor core) ----------------
__global__ __launch_bounds__(128) void k_flash_light() {
    __shared__ __half sQ[64 * 72], sK[64 * 72], sV[64 * 72];
    int idx = blockIdx.x;
    int w = idx & (NWIN - 1), h = (idx >> 7) & 7, b = idx >> 10;
    int tid = threadIdx.x, lane = tid & 31, warp = tid >> 5;
    const __half* qb_ = g_qkvh + (size_t)(b * SEQ + w * 64) * 1536 + h * 64;
    for (int i = tid; i < 64 * 8; i += 128) {
        int r = i >> 3, c = (i & 7) * 8;
        *(float4*)&sQ[r * 72 + c] = *(const float4*)(qb_ + (size_t)r * 1536 + c);
    }
    __syncthreads();
    unsigned af[4][4];
    int q0w = warp * 16;
    #pragma unroll
    for (int kc = 0; kc < 4; kc++)
        ldsm_x4(af[kc], saddr(&sQ[(q0w + (lane & 15)) * 72 + kc * 16 + ((lane >> 4) & 1) * 8]));
    float o[8][4];
    #pragma unroll
    for (int nt = 0; nt < 8; nt++)
        #pragma unroll
        for (int i = 0; i < 4; i++) o[nt][i] = 0.0f;
    float m[2] = {-1e30f, -1e30f}, l[2] = {0.0f, 0.0f};
    for (int kw = w - 1; kw <= w + 1; kw++) {
        if (kw < 0 || kw >= NWIN) continue;
        __syncthreads();
        const __half* kb_ = g_qkvh + (size_t)(b * SEQ + kw * 64) * 1536 + 512 + h * 64;
        const __half* vb_ = kb_ + 512;
        for (int i = tid; i < 64 * 8; i += 128) {
            int r = i >> 3, c = (i & 7) * 8;
            *(float4*)&sK[r * 72 + c] = *(const float4*)(kb_ + (size_t)r * 1536 + c);
            *(float4*)&sV[r * 72 + c] = *(const float4*)(vb_ + (size_t)r * 1536 + c);
        }
        __syncthreads();
        #pragma unroll
        for (int kb = 0; kb < 64; kb += 16)
            flash_kb(sK, sV, kb, 0, INT_MAX, af, o, m, l, lane);
    }
    l[0] += __shfl_xor_sync(0xffffffffu, l[0], 1);
    l[0] += __shfl_xor_sync(0xffffffffu, l[0], 2);
    l[1] += __shfl_xor_sync(0xffffffffu, l[1], 1);
    l[1] += __shfl_xor_sync(0xffffffffu, l[1], 2);
    float inv0 = 1.0f / l[0], inv1 = 1.0f / l[1];
    int r0 = b * SEQ + w * 64 + q0w + (lane >> 2);
    #pragma unroll
    for (int nt = 0; nt < 8; nt++) {
        int c = h * 64 + nt * 8 + (lane & 3) * 2;
        *(unsigned*)&g_loh[(size_t)r0 * 512 + c]       = h2pack(o[nt][0] * inv0, o[nt][1] * inv0);
        *(unsigned*)&g_loh[(size_t)(r0 + 8) * 512 + c] = h2pack(o[nt][2] * inv1, o[nt][3] * inv1);
    }
}

// ---------------- 7. build heavy K/V (fp16, padded) ----------------
__global__ void k_kvprep(const float* __restrict__ null_kv) {
    const int total = BATCH * HEADS * NKEYP * DH;
    for (int i = blockIdx.x * blockDim.x + threadIdx.x; i < total; i += gridDim.x * blockDim.x) {
        int d = i & (DH - 1);
        int j = (i >> 6) % NKEYP;
        int h = (i / (DH * NKEYP)) % HEADS;
        int b = i / (DH * NKEYP * HEADS);
        float kv = 0.0f, vv = 0.0f;
        if (j == 0) {
            kv = null_kv[h * DH + d];
            vv = null_kv[HEADS * DH + h * DH + d];
        } else if (j < NKEY) {
            size_t rowo = ((size_t)(b * NKV + j - 1)) * DIM + h * 2 * DH;
            kv = g_kvh[rowo + d];
            vv = g_kvh[rowo + DH + d] * g_skv[b][j - 1];
        }
        g_khh[i] = __float2half(kv);
        g_vhh[i] = __float2half(vv);
    }
}

// ---------------- 8. heavy attention (tensor core flash) ----------------
__global__ __launch_bounds__(128) void k_flash_heavy() {
    __shared__ __half sQ[64 * 72], sK[64 * 72], sV[64 * 72];
    int idx = blockIdx.x;
    int qc = idx & 15, h = (idx >> 4) & 7, b = idx >> 7;
    int tid = threadIdx.x, lane = tid & 31, warp = tid >> 5;
    const __half* qb_ = g_qhh + (size_t)(b * NQ + qc * 64) * 512 + h * 64;
    for (int i = tid; i < 64 * 8; i += 128) {
        int r = i >> 3, c = (i & 7) * 8;
        *(float4*)&sQ[r * 72 + c] = *(const float4*)(qb_ + (size_t)r * 512 + c);
    }
    __syncthreads();
    unsigned af[4][4];
    int q0w = warp * 16;
    #pragma unroll
    for (int kc = 0; kc < 4; kc++)
        ldsm_x4(af[kc], saddr(&sQ[(q0w + (lane & 15)) * 72 + kc * 16 + ((lane >> 4) & 1) * 8]));
    float o[8][4];
    #pragma unroll
    for (int nt = 0; nt < 8; nt++)
        #pragma unroll
        for (int i = 0; i < 4; i++) o[nt][i] = 0.0f;
    float m[2] = {-1e30f, -1e30f}, l[2] = {0.0f, 0.0f};
    const __half* kbase = g_khh + (size_t)(b * HEADS + h) * NKEYP * DH;
    const __half* vbase = g_vhh + (size_t)(b * HEADS + h) * NKEYP * DH;
    for (int chunk = 0; chunk < NKEYP; chunk += 64) {
        __syncthreads();
        for (int i = tid; i < 64 * 8; i += 128) {
            int r = i >> 3, c = (i & 7) * 8;
            *(float4*)&sK[r * 72 + c] = *(const float4*)(kbase + (size_t)(chunk + r) * 64 + c);
            *(float4*)&sV[r * 72 + c] = *(const float4*)(vbase + (size_t)(chunk + r) * 64 + c);
        }
        __syncthreads();
        int nkb = NKEY - chunk;
        nkb = nkb > 64 ? 64 : ((nkb + 15) & ~15);
        for (int kb = 0; kb < nkb; kb += 16)
            flash_kb(sK, sV, kb, chunk + kb, NKEY, af, o, m, l, lane);
    }
    l[0] += __shfl_xor_sync(0xffffffffu, l[0], 1);
    l[0] += __shfl_xor_sync(0xffffffffu, l[0], 2);
    l[1] += __shfl_xor_sync(0xffffffffu, l[1], 1);
    l[1] += __shfl_xor_sync(0xffffffffu, l[1], 2);
    float inv0 = 1.0f / l[0], inv1 = 1.0f / l[1];
    int r0 = b * NQ + qc * 64 + q0w + (lane >> 2);
    #pragma unroll
    for (int nt = 0; nt < 8; nt++) {
        int c = h * 64 + nt * 8 + (lane & 3) * 2;
        *(unsigned*)&g_hoh[(size_t)r0 * 512 + c]       = h2pack(o[nt][0] * inv0, o[nt][1] * inv0);
        *(unsigned*)&g_hoh[(size_t)(r0 + 8) * 512 + c] = h2pack(o[nt][2] * inv1, o[nt][3] * inv1);
    }
}

// ---------------- 9. combine (vectorized) ----------------
__global__ __launch_bounds__(256) void k_combine(float* __restrict__ out,
                                                 const float* __restrict__ null_q) {
    int row = blockIdx.x, tid = threadIdx.x;
    int pos = g_qpos[row];
    float4* orow = (float4*)(out + (size_t)row * DIM);
    float4 o = orow[tid];
    if (pos >= 0) {
        int b = row / SEQ;
        float sq = g_sq[b][pos];
        float4 rr = *(const float4*)(g_routed + ((size_t)(b * NQ + pos)) * DIM + tid * 4);
        o.x += rr.x * sq; o.y += rr.y * sq; o.z += rr.z * sq; o.w += rr.w * sq;
    } else {
        float4 nq = *(const float4*)(null_q + tid * 4);
        o.x += nq.x; o.y += nq.y; o.z += nq.z; o.w += nq.w;
    }
    orow[tid] = o;
}

// ---------------- launcher ----------------
extern "C" void kernel_launch(void* const* d_in, const int* in_sizes, int n_in,
                              void* d_out, int out_size) {
    const float* x       = (const float*)d_in[0];
    const float* ln_g    = (const float*)d_in[1];
    const float* ln_b    = (const float*)d_in[2];
    const float* w_qkv_l = (const float*)d_in[3];
    const float* w_out_l = (const float*)d_in[4];
    const float* null_q  = (const float*)d_in[5];
    const float* rt_q    = (const float*)d_in[6];
    const float* rt_kv   = (const float*)d_in[7];
    const float* rms_g   = (const float*)d_in[8];
    const float* w_q_h   = (const float*)d_in[9];
    const float* w_kv_h  = (const float*)d_in[10];
    const float* null_kv = (const float*)d_in[11];
    const float* w_out_h = (const float*)d_in[12];
    float* out = (float*)d_out;

    void *p_xnh, *p_qkvh, *p_loh, *p_xqnh, *p_xkvnh, *p_qhh, *p_kvh, *p_hoh, *p_routed;
    void *p_wqkvh, *p_wolh, *p_wqh, *p_wkvh, *p_wohh;
    cudaGetSymbolAddress(&p_xnh, g_xnh);
    cudaGetSymbolAddress(&p_qkvh, g_qkvh);
    cudaGetSymbolAddress(&p_loh, g_loh);
    cudaGetSymbolAddress(&p_xqnh, g_xqnh);
    cudaGetSymbolAddress(&p_xkvnh, g_xkvnh);
    cudaGetSymbolAddress(&p_qhh, g_qhh);
    cudaGetSymbolAddress(&p_kvh, g_kvh);
    cudaGetSymbolAddress(&p_hoh, g_hoh);
    cudaGetSymbolAddress(&p_routed, g_routed);
    cudaGetSymbolAddress(&p_wqkvh, g_wqkvh);
    cudaGetSymbolAddress(&p_wolh, g_wolh);
    cudaGetSymbolAddress(&p_wqh, g_wqh);
    cudaGetSymbolAddress(&p_wkvh, g_wkvh);
    cudaGetSymbolAddress(&p_wohh, g_wohh);

    cudaFuncSetAttribute(k_route, cudaFuncAttributeMaxDynamicSharedMemorySize, SEQ * 8);
    cudaFuncSetAttribute(k_hgemm<float>,  cudaFuncAttributeMaxDynamicSharedMemorySize, SMEM_GEMM);
    cudaFuncSetAttribute(k_hgemm<__half>, cudaFuncAttributeMaxDynamicSharedMemorySize, SMEM_GEMM);

    k_f2h_all<<<512, 256>>>(w_qkv_l, w_out_l, w_q_h, w_kv_h, w_out_h);
    k_ln<<<NTOK, 256>>>(x, ln_g, ln_b, rt_q, rt_kv);
    k_route<<<4, 1024, SEQ * 8>>>();
    k_gather<<<BATCH * (NQ + NKV), 256>>>(x, rms_g);

    // light path
    k_hgemm<__half><<<dim3((3 * HDH) / GBN, NTOK / GBM), 256, SMEM_GEMM>>>((const __half*)p_xnh, (const __half*)p_wqkvh, (__half*)p_qkvh, NTOK, 3 * HDH, DIM);
    k_flash_light<<<BATCH * HEADS * NWIN, 128>>>();
    k_hgemm<float><<<dim3(DIM / GBN, NTOK / GBM), 256, SMEM_GEMM>>>((const __half*)p_loh, (const __half*)p_wolh, out, NTOK, DIM, HDH);

    // heavy path
    k_hgemm<__half><<<dim3(HDH / GBN, (BATCH * NQ) / GBM), 256, SMEM_GEMM>>>((const __half*)p_xqnh, (const __half*)p_wqh, (__half*)p_qhh, BATCH * NQ, HDH, DIM);
    k_hgemm<float><<<dim3(DIM / GBN, (BATCH * NKV) / GBM), 256, SMEM_GEMM>>>((const __half*)p_xkvnh, (const __half*)p_wkvh, (float*)p_kvh, BATCH * NKV, DIM, DIM);
    k_kvprep<<<1024, 256>>>(null_kv);
    k_flash_heavy<<<BATCH * HEADS * (NQ / 64), 128>>>();
    k_hgemm<float><<<dim3(DIM / GBN, (BATCH * NQ) / GBM), 256, SMEM_GEMM>>>((const __half*)p_hoh, (const __half*)p_wohh, (float*)p_routed, BATCH * NQ, DIM, HDH);

    k_combine<<<NTOK, 256>>>(out, null_q);
}